// round 1
// baseline (speedup 1.0000x reference)
#include <cuda_runtime.h>

#define BB 8
#define NN 2048
#define FIN 256
#define FOUT 256
#define ALPHA 0.2f

// Scratch (allocation-free rule: __device__ globals)
__device__ float g_Wh[(size_t)BB * NN * FOUT];   // 16.8 MB
__device__ float g_fi[BB * NN];
__device__ float g_fj[BB * NN];

// ---------------------------------------------------------------------------
// Kernel 1: Wh[b,n,o] = sum_f h[b,n,f] * W[o,f]
// Block: 256 threads, tile = 64 rows x 256 cols, K chunks of 32.
// Per-thread micro-tile: 4 rows x 16 cols.
// ---------------------------------------------------------------------------
__global__ __launch_bounds__(256) void wh_kernel(const float* __restrict__ h,
                                                 const float* __restrict__ W) {
    __shared__ float hs[32][64 + 4];    // [k][n]
    __shared__ float ws[32][256 + 4];   // [k][o]

    const int b  = blockIdx.y;
    const int n0 = blockIdx.x * 64;
    const int t  = threadIdx.x;
    const int tx = t & 15;       // col group
    const int ty = t >> 4;       // row group
    const int c0 = tx * 16;
    const int r0 = ty * 4;

    float acc[4][16];
#pragma unroll
    for (int r = 0; r < 4; r++)
#pragma unroll
        for (int c = 0; c < 16; c++) acc[r][c] = 0.f;

    const float* hb = h + ((size_t)b * NN + n0) * FIN;

    for (int kk = 0; kk < FIN; kk += 32) {
        // h tile: 64x32 floats = 512 float4, 2 per thread
#pragma unroll
        for (int l = 0; l < 2; l++) {
            int idx = t + l * 256;           // 0..511
            int n   = idx >> 3;
            int k4  = (idx & 7) * 4;
            float4 v = *(const float4*)(hb + (size_t)n * FIN + kk + k4);
            hs[k4 + 0][n] = v.x; hs[k4 + 1][n] = v.y;
            hs[k4 + 2][n] = v.z; hs[k4 + 3][n] = v.w;
        }
        // W tile: 256x32 floats = 2048 float4, 8 per thread
#pragma unroll
        for (int l = 0; l < 8; l++) {
            int idx = t + l * 256;           // 0..2047
            int o   = idx >> 3;
            int k4  = (idx & 7) * 4;
            float4 v = *(const float4*)(W + (size_t)o * FIN + kk + k4);
            ws[k4 + 0][o] = v.x; ws[k4 + 1][o] = v.y;
            ws[k4 + 2][o] = v.z; ws[k4 + 3][o] = v.w;
        }
        __syncthreads();

#pragma unroll
        for (int k = 0; k < 32; k++) {
            float av[4];
            float4 a4 = *(const float4*)&hs[k][r0];
            av[0] = a4.x; av[1] = a4.y; av[2] = a4.z; av[3] = a4.w;
            float bv[16];
#pragma unroll
            for (int c4 = 0; c4 < 4; c4++) {
                float4 b4 = *(const float4*)&ws[k][c0 + c4 * 4];
                bv[c4 * 4 + 0] = b4.x; bv[c4 * 4 + 1] = b4.y;
                bv[c4 * 4 + 2] = b4.z; bv[c4 * 4 + 3] = b4.w;
            }
#pragma unroll
            for (int r = 0; r < 4; r++)
#pragma unroll
                for (int c = 0; c < 16; c++) acc[r][c] += av[r] * bv[c];
        }
        __syncthreads();
    }

    // Store Wh tile
#pragma unroll
    for (int r = 0; r < 4; r++) {
        float* dst = g_Wh + ((size_t)b * NN + n0 + r0 + r) * FOUT + c0;
#pragma unroll
        for (int c4 = 0; c4 < 4; c4++) {
            float4 v;
            v.x = acc[r][c4 * 4 + 0]; v.y = acc[r][c4 * 4 + 1];
            v.z = acc[r][c4 * 4 + 2]; v.w = acc[r][c4 * 4 + 3];
            *(float4*)(dst + c4 * 4) = v;
        }
    }
}

// ---------------------------------------------------------------------------
// Kernel 2: f_i[row] = Wh[row,:] . a1 ;  f_j[row] = Wh[row,:] . a2
// One block (256 threads) per row.
// ---------------------------------------------------------------------------
__global__ __launch_bounds__(256) void fij_kernel(const float* __restrict__ a) {
    const int row = blockIdx.x;              // 0 .. B*N-1
    const int t   = threadIdx.x;             // 0 .. 255
    float v  = g_Wh[(size_t)row * FOUT + t];
    float s1 = v * a[t];
    float s2 = v * a[FOUT + t];
#pragma unroll
    for (int off = 16; off; off >>= 1) {
        s1 += __shfl_down_sync(0xFFFFFFFFu, s1, off);
        s2 += __shfl_down_sync(0xFFFFFFFFu, s2, off);
    }
    __shared__ float r1[8], r2[8];
    if ((t & 31) == 0) { r1[t >> 5] = s1; r2[t >> 5] = s2; }
    __syncthreads();
    if (t == 0) {
        float x1 = 0.f, x2 = 0.f;
#pragma unroll
        for (int w = 0; w < 8; w++) { x1 += r1[w]; x2 += r2[w]; }
        g_fi[row] = x1;
        g_fj[row] = x2;
    }
}

// ---------------------------------------------------------------------------
// Kernel 3: out[b,i,:] = (sum_j w_ij * Wh[b,j,:]) / (sum_j w_ij)
//           w_ij = adj[b,i,j] ? exp(leaky(f_i[b,i] + f_j[b,j])) : 0
// Block: 256 threads, 64 i-rows x 256 channels; j in chunks of 32.
// Per-thread micro-tile: 4 rows x 16 cols + 4 denominators.
// ---------------------------------------------------------------------------
__global__ __launch_bounds__(256) void attn_kernel(const int* __restrict__ adj,
                                                   float* __restrict__ out) {
    __shared__ float whs[32][256 + 4];  // [j][o]
    __shared__ float ps [32][64 + 4];   // [j][i]  (weights, transposed)
    __shared__ float fis[64];
    __shared__ float fjs[32];

    const int b  = blockIdx.y;
    const int i0 = blockIdx.x * 64;
    const int t  = threadIdx.x;
    const int tx = t & 15;
    const int ty = t >> 4;
    const int c0 = tx * 16;
    const int r0 = ty * 4;

    if (t < 64) fis[t] = g_fi[b * NN + i0 + t];

    float acc[4][16];
#pragma unroll
    for (int r = 0; r < 4; r++)
#pragma unroll
        for (int c = 0; c < 16; c++) acc[r][c] = 0.f;
    float den[4] = {0.f, 0.f, 0.f, 0.f};

    const int*   adjb = adj + ((size_t)b * NN + i0) * NN;
    const float* whb  = g_Wh + (size_t)b * NN * FOUT;

    for (int j0 = 0; j0 < NN; j0 += 32) {
        __syncthreads();  // previous chunk's compute done before overwrite

        // Load Wh[j0..j0+31, :] -> whs (2048 float4, 8 per thread, same layout)
#pragma unroll
        for (int l = 0; l < 8; l++) {
            int idx = t + l * 256;           // 0..2047
            int j   = idx >> 6;
            int o4  = (idx & 63) * 4;
            float4 v = *(const float4*)(whb + (size_t)(j0 + j) * FOUT + o4);
            *(float4*)&whs[j][o4] = v;
        }
        if (t < 32) fjs[t] = g_fj[b * NN + j0 + t];
        __syncthreads();  // fjs visible for weight generation

        // Generate weight tile: 64x32, 8 per thread. Warp w handles rows 8w..8w+7,
        // lane = j -> coalesced 128B adj reads per row.
        {
            const int j  = t & 31;
            const int ib = (t >> 5) * 8;
            const float fj = fjs[j];
#pragma unroll
            for (int q = 0; q < 8; q++) {
                int i = ib + q;
                int av = adjb[(size_t)i * NN + j0 + j];
                float e = fis[i] + fj;
                e = (e > 0.f) ? e : ALPHA * e;
                ps[j][i] = av ? __expf(e) : 0.f;
            }
        }
        __syncthreads();  // ps + whs visible for accumulation

        // Accumulate: acc[r][c] += ps[j][r0+r] * whs[j][c0+c]
#pragma unroll 4
        for (int j = 0; j < 32; j++) {
            float4 p4 = *(const float4*)&ps[j][r0];
            den[0] += p4.x; den[1] += p4.y; den[2] += p4.z; den[3] += p4.w;
            float bv[16];
#pragma unroll
            for (int c4 = 0; c4 < 4; c4++) {
                float4 b4 = *(const float4*)&whs[j][c0 + c4 * 4];
                bv[c4 * 4 + 0] = b4.x; bv[c4 * 4 + 1] = b4.y;
                bv[c4 * 4 + 2] = b4.z; bv[c4 * 4 + 3] = b4.w;
            }
            float pv[4] = {p4.x, p4.y, p4.z, p4.w};
#pragma unroll
            for (int r = 0; r < 4; r++)
#pragma unroll
                for (int c = 0; c < 16; c++) acc[r][c] += pv[r] * bv[c];
        }
    }

    // Epilogue: divide by denominator, store
#pragma unroll
    for (int r = 0; r < 4; r++) {
        float inv = 1.0f / den[r];
        float* dst = out + ((size_t)b * NN + i0 + r0 + r) * FOUT + c0;
#pragma unroll
        for (int c4 = 0; c4 < 4; c4++) {
            float4 v;
            v.x = acc[r][c4 * 4 + 0] * inv; v.y = acc[r][c4 * 4 + 1] * inv;
            v.z = acc[r][c4 * 4 + 2] * inv; v.w = acc[r][c4 * 4 + 3] * inv;
            *(float4*)(dst + c4 * 4) = v;
        }
    }
}

// ---------------------------------------------------------------------------
extern "C" void kernel_launch(void* const* d_in, const int* in_sizes, int n_in,
                              void* d_out, int out_size) {
    const float* h   = (const float*)d_in[0];
    const int*   adj = (const int*)d_in[1];
    const float* W   = (const float*)d_in[2];
    const float* a   = (const float*)d_in[3];
    float*       out = (float*)d_out;

    dim3 g1(NN / 64, BB);
    wh_kernel<<<g1, 256>>>(h, W);
    fij_kernel<<<BB * NN, 256>>>(a);
    dim3 g3(NN / 64, BB);
    attn_kernel<<<g3, 256>>>(adj, out);
}

// round 4
// speedup vs baseline: 4.8978x; 4.8978x over previous
#include <cuda_runtime.h>
#include <cstdint>

#define BB 8
#define NN 2048
#define FIN 256
#define FOUT 256
#define ALPHA 0.2f

// Scratch (allocation-free rule: __device__ globals)
__device__ float g_Wh [(size_t)BB * NN * FOUT];   // 16.8 MB  [b][n][o]
__device__ float g_WhT[(size_t)BB * FOUT * NN];   // 16.8 MB  [b][o][n]
__device__ float g_fi[BB * NN];
__device__ float g_fj[BB * NN];

__device__ __forceinline__ uint32_t to_tf32(float x) {
    uint32_t r;
    asm("cvt.rna.tf32.f32 %0, %1;" : "=r"(r) : "f"(x));
    return r;
}

// mma.sync m16n8k8 tf32: D += A*B, A row-major 16x8, B col-major 8x8 (K-major)
__device__ __forceinline__ void mma_tf32(float* d, const uint32_t* a,
                                         uint32_t b0, uint32_t b1) {
    asm volatile(
        "mma.sync.aligned.m16n8k8.row.col.f32.tf32.tf32.f32 "
        "{%0,%1,%2,%3}, {%4,%5,%6,%7}, {%8,%9}, {%0,%1,%2,%3};\n"
        : "+f"(d[0]), "+f"(d[1]), "+f"(d[2]), "+f"(d[3])
        : "r"(a[0]), "r"(a[1]), "r"(a[2]), "r"(a[3]), "r"(b0), "r"(b1));
}

// Shared-memory geometry for the two GEMM kernels (dynamic smem):
//   As: 128 rows x 36 stride (tf32 bits)   -> 4608 words
//   Bs: 256 rows x 36 stride (tf32 bits)   -> 9216 words
//   fis/denbuf: 128 + 128 floats           (attn only)
#define AS_WORDS  (128 * 36)
#define BS_WORDS  (256 * 36)
#define SMEM_WORDS (AS_WORDS + BS_WORDS + 256)
#define SMEM_BYTES (SMEM_WORDS * 4)
#define KC 32

// ---------------------------------------------------------------------------
// Kernel 1: Wh = h @ W^T  via mma.sync tf32.
// CTA: 128 n-rows x 256 o-cols, 512 threads (16 warps, 4x4), K=FIN in chunks of 32.
// ---------------------------------------------------------------------------
__global__ __launch_bounds__(512) void wh_kernel(const float* __restrict__ h,
                                                 const float* __restrict__ W) {
    extern __shared__ uint32_t dyn[];
    uint32_t* As = dyn;
    uint32_t* Bs = dyn + AS_WORDS;

    const int t    = threadIdx.x;
    const int wid  = t >> 5;
    const int lane = t & 31;
    const int g    = lane >> 2;
    const int c    = lane & 3;
    const int wm   = wid & 3;        // 0..3 -> 32-row slice
    const int wn   = wid >> 2;       // 0..3 -> 64-col slice
    const int b    = blockIdx.y;
    const int n0   = blockIdx.x * 128;

    float acc[2][8][4];
#pragma unroll
    for (int mt = 0; mt < 2; mt++)
#pragma unroll
        for (int nt = 0; nt < 8; nt++)
#pragma unroll
            for (int x = 0; x < 4; x++) acc[mt][nt][x] = 0.f;

    const float* hb = h + ((size_t)b * NN + n0) * FIN;

    for (int kk = 0; kk < FIN; kk += KC) {
        __syncthreads();   // previous chunk's compute done
        // A tile: h[128][32] -> As  (1024 float4, 2 per thread)
#pragma unroll
        for (int l = 0; l < 2; l++) {
            int idx = t + l * 512;
            int n   = idx >> 3;
            int c4  = (idx & 7) * 4;
            float4 v = *(const float4*)(hb + (size_t)n * FIN + kk + c4);
            uint32_t* dst = &As[n * 36 + c4];
            dst[0] = to_tf32(v.x); dst[1] = to_tf32(v.y);
            dst[2] = to_tf32(v.z); dst[3] = to_tf32(v.w);
        }
        // B tile: W[256][32] -> Bs (2048 float4, 4 per thread)
#pragma unroll
        for (int l = 0; l < 4; l++) {
            int idx = t + l * 512;
            int o   = idx >> 3;
            int c4  = (idx & 7) * 4;
            float4 v = *(const float4*)(W + (size_t)o * FIN + kk + c4);
            uint32_t* dst = &Bs[o * 36 + c4];
            dst[0] = to_tf32(v.x); dst[1] = to_tf32(v.y);
            dst[2] = to_tf32(v.z); dst[3] = to_tf32(v.w);
        }
        __syncthreads();

#pragma unroll
        for (int ks = 0; ks < 4; ks++) {
            const int k8 = ks * 8;
            uint32_t a[2][4];
#pragma unroll
            for (int mt = 0; mt < 2; mt++) {
                int r = wm * 32 + mt * 16;
                a[mt][0] = As[(r + g    ) * 36 + k8 + c];
                a[mt][1] = As[(r + g + 8) * 36 + k8 + c];
                a[mt][2] = As[(r + g    ) * 36 + k8 + c + 4];
                a[mt][3] = As[(r + g + 8) * 36 + k8 + c + 4];
            }
#pragma unroll
            for (int nt = 0; nt < 8; nt++) {
                int o = wn * 64 + nt * 8 + g;
                uint32_t b0 = Bs[o * 36 + k8 + c];
                uint32_t b1 = Bs[o * 36 + k8 + c + 4];
                mma_tf32(acc[0][nt], a[0], b0, b1);
                mma_tf32(acc[1][nt], a[1], b0, b1);
            }
        }
    }

    // Epilogue: float2 stores (32B sectors per quad -> fully coalesced)
#pragma unroll
    for (int mt = 0; mt < 2; mt++) {
        int ia = n0 + wm * 32 + mt * 16 + g;
#pragma unroll
        for (int nt = 0; nt < 8; nt++) {
            int o = wn * 64 + nt * 8 + 2 * c;
            float2 va = make_float2(acc[mt][nt][0], acc[mt][nt][1]);
            float2 vb = make_float2(acc[mt][nt][2], acc[mt][nt][3]);
            *(float2*)(g_Wh + ((size_t)b * NN + ia    ) * FOUT + o) = va;
            *(float2*)(g_Wh + ((size_t)b * NN + ia + 8) * FOUT + o) = vb;
        }
    }
}

// ---------------------------------------------------------------------------
// Kernel 1b: g_WhT[b][o][n] = g_Wh[b][n][o]
// ---------------------------------------------------------------------------
__global__ __launch_bounds__(256) void wht_kernel() {
    __shared__ float tile[32][33];
    const int b  = blockIdx.z;
    const int n0 = blockIdx.x * 32;
    const int o0 = blockIdx.y * 32;
    const int tx = threadIdx.x, ty = threadIdx.y;
    const float* src = g_Wh + (size_t)b * NN * FOUT;
#pragma unroll
    for (int k = 0; k < 4; k++) {
        int n = n0 + ty + k * 8;
        tile[ty + k * 8][tx] = src[(size_t)n * FOUT + o0 + tx];
    }
    __syncthreads();
    float* dst = g_WhT + (size_t)b * FOUT * NN;
#pragma unroll
    for (int k = 0; k < 4; k++) {
        int o = o0 + ty + k * 8;
        dst[(size_t)o * NN + n0 + tx] = tile[tx][ty + k * 8];
    }
}

// ---------------------------------------------------------------------------
// Kernel 2: f_i = Wh . a1 ; f_j = Wh . a2   (per row)
// ---------------------------------------------------------------------------
__global__ __launch_bounds__(256) void fij_kernel(const float* __restrict__ a) {
    const int row = blockIdx.x;
    const int t   = threadIdx.x;
    float v  = g_Wh[(size_t)row * FOUT + t];
    float s1 = v * a[t];
    float s2 = v * a[FOUT + t];
#pragma unroll
    for (int off = 16; off; off >>= 1) {
        s1 += __shfl_down_sync(0xFFFFFFFFu, s1, off);
        s2 += __shfl_down_sync(0xFFFFFFFFu, s2, off);
    }
    __shared__ float r1[8], r2[8];
    if ((t & 31) == 0) { r1[t >> 5] = s1; r2[t >> 5] = s2; }
    __syncthreads();
    if (t == 0) {
        float x1 = 0.f, x2 = 0.f;
#pragma unroll
        for (int w = 0; w < 8; w++) { x1 += r1[w]; x2 += r2[w]; }
        g_fi[row] = x1;
        g_fj[row] = x2;
    }
}

// ---------------------------------------------------------------------------
// Kernel 3: out[b,i,:] = (sum_j w_ij * Wh[b,j,:]) / (sum_j w_ij)
//   w_ij = adj[b,i,j] ? exp(leaky(f_i + f_j)) : 0
// CTA: 128 i-rows x 256 o-cols, 512 threads, j chunks of 32, mma.sync tf32.
// ---------------------------------------------------------------------------
__global__ __launch_bounds__(512) void attn_kernel(const int* __restrict__ adj,
                                                   float* __restrict__ out) {
    extern __shared__ uint32_t dyn[];
    uint32_t* As    = dyn;                       // P tile, 128 x 36
    uint32_t* Bs    = dyn + AS_WORDS;            // WhT tile, 256 x 36
    float*   fis    = (float*)(dyn + AS_WORDS + BS_WORDS);  // 128
    float*   denbuf = fis + 128;                 // 128

    const int t    = threadIdx.x;
    const int wid  = t >> 5;
    const int lane = t & 31;
    const int g    = lane >> 2;
    const int c    = lane & 3;
    const int wm   = wid & 3;
    const int wn   = wid >> 2;
    const int b    = blockIdx.y;
    const int i0   = blockIdx.x * 128;

    if (t < 128) fis[t] = g_fi[b * NN + i0 + t];

    float acc[2][8][4];
#pragma unroll
    for (int mt = 0; mt < 2; mt++)
#pragma unroll
        for (int nt = 0; nt < 8; nt++)
#pragma unroll
            for (int x = 0; x < 4; x++) acc[mt][nt][x] = 0.f;

    float den_part[8];
#pragma unroll
    for (int q = 0; q < 8; q++) den_part[q] = 0.f;

    const int*   adjb = adj   + ((size_t)b * NN + i0) * NN;
    const float* whtb = g_WhT + (size_t)b * FOUT * NN;
    const float* fjb  = g_fj  + b * NN;

    for (int j0 = 0; j0 < NN; j0 += KC) {
        __syncthreads();   // previous chunk's compute done (and fis ready at c=0)

        // B tile: WhT[256][j0..j0+31] -> Bs (2048 float4, 4 per thread)
#pragma unroll
        for (int l = 0; l < 4; l++) {
            int idx = t + l * 512;
            int o   = idx >> 3;
            int c4  = (idx & 7) * 4;
            float4 v = *(const float4*)(whtb + (size_t)o * NN + j0 + c4);
            uint32_t* dst = &Bs[o * 36 + c4];
            dst[0] = to_tf32(v.x); dst[1] = to_tf32(v.y);
            dst[2] = to_tf32(v.z); dst[3] = to_tf32(v.w);
        }

        // P tile: warp wid owns rows 8*wid..8*wid+7, lane = j (coalesced adj)
        {
            const float fj = fjb[j0 + lane];
#pragma unroll
            for (int q = 0; q < 8; q++) {
                int i  = wid * 8 + q;
                int av = adjb[(size_t)i * NN + j0 + lane];
                float e  = fis[i] + fj;
                e = fmaxf(e, ALPHA * e);
                float wv = av ? __expf(e) : 0.f;
                den_part[q] += wv;
                As[i * 36 + lane] = to_tf32(wv);
            }
        }
        __syncthreads();

#pragma unroll
        for (int ks = 0; ks < 4; ks++) {
            const int k8 = ks * 8;
            uint32_t a[2][4];
#pragma unroll
            for (int mt = 0; mt < 2; mt++) {
                int r = wm * 32 + mt * 16;
                a[mt][0] = As[(r + g    ) * 36 + k8 + c];
                a[mt][1] = As[(r + g + 8) * 36 + k8 + c];
                a[mt][2] = As[(r + g    ) * 36 + k8 + c + 4];
                a[mt][3] = As[(r + g + 8) * 36 + k8 + c + 4];
            }
#pragma unroll
            for (int nt = 0; nt < 8; nt++) {
                int o = wn * 64 + nt * 8 + g;
                uint32_t b0 = Bs[o * 36 + k8 + c];
                uint32_t b1 = Bs[o * 36 + k8 + c + 4];
                mma_tf32(acc[0][nt], a[0], b0, b1);
                mma_tf32(acc[1][nt], a[1], b0, b1);
            }
        }
    }

    // Denominators: reduce over lanes (j); row i = wid*8+q
#pragma unroll
    for (int q = 0; q < 8; q++) {
        float v = den_part[q];
#pragma unroll
        for (int off = 16; off; off >>= 1) v += __shfl_xor_sync(0xFFFFFFFFu, v, off);
        if (lane == 0) denbuf[wid * 8 + q] = v;
    }
    __syncthreads();

    // Epilogue: divide + float2 stores
#pragma unroll
    for (int mt = 0; mt < 2; mt++) {
        int ra = wm * 32 + mt * 16 + g;       // local row (lo)
        int rb = ra + 8;                      // local row (hi)
        float inva = 1.0f / denbuf[ra];
        float invb = 1.0f / denbuf[rb];
#pragma unroll
        for (int nt = 0; nt < 8; nt++) {
            int o = wn * 64 + nt * 8 + 2 * c;
            float2 va = make_float2(acc[mt][nt][0] * inva, acc[mt][nt][1] * inva);
            float2 vb = make_float2(acc[mt][nt][2] * invb, acc[mt][nt][3] * invb);
            *(float2*)(out + ((size_t)b * NN + i0 + ra) * FOUT + o) = va;
            *(float2*)(out + ((size_t)b * NN + i0 + rb) * FOUT + o) = vb;
        }
    }
}

// ---------------------------------------------------------------------------
extern "C" void kernel_launch(void* const* d_in, const int* in_sizes, int n_in,
                              void* d_out, int out_size) {
    const float* h   = (const float*)d_in[0];
    const int*   adj = (const int*)d_in[1];
    const float* W   = (const float*)d_in[2];
    const float* a   = (const float*)d_in[3];
    float*       out = (float*)d_out;

    cudaFuncSetAttribute(wh_kernel, cudaFuncAttributeMaxDynamicSharedMemorySize,
                         SMEM_BYTES);
    cudaFuncSetAttribute(attn_kernel, cudaFuncAttributeMaxDynamicSharedMemorySize,
                         SMEM_BYTES);

    dim3 g1(NN / 128, BB);
    wh_kernel<<<g1, 512, SMEM_BYTES>>>(h, W);
    dim3 gt(NN / 32, FOUT / 32, BB);
    wht_kernel<<<gt, dim3(32, 8)>>>();
    fij_kernel<<<BB * NN, 256>>>(a);
    dim3 g3(NN / 128, BB);
    attn_kernel<<<g3, 512, SMEM_BYTES>>>(adj, out);
}